// round 8
// baseline (speedup 1.0000x reference)
#include <cuda_runtime.h>
#include <cuda_fp16.h>
#include <math.h>

#define BATCH 8
#define TD 256
#define TE 256
#define DIN 80
#define D 512
#define MEL 80
#define ROWS (BATCH*TD)          // 2048
#define CLSZ 16

// ----------------------------- scratch (device globals) ---------------------
__device__ __align__(16) float g_Xg[ROWS * 4 * D];        // inputs@Wk + b : [2048][2048]
__device__ __align__(16) float g_h1[ROWS * D];            // attended@W1+b1: [2048][512]
__device__ __align__(16) float g_h2[ROWS * D];            // x@W1+b1      : [2048][512]
__device__ __align__(16) float g_XC[ROWS * 2 * D];        // [x | weighted]: [2048][1024]
__device__ __align__(16) float g_scores[BATCH * TD * TE]; // scores/attn   : [2048][256]
__device__ __align__(16) float g_part[4 * ROWS * D];      // split-K partials

// ----------------------------- helpers --------------------------------------
__device__ __forceinline__ float fast_tanh(float x) {
    float y;
    asm("tanh.approx.f32 %0, %1;" : "=f"(y) : "f"(x));
    return y;
}
__device__ __forceinline__ unsigned smem_u32(const void* p) {
    unsigned a;
    asm("{ .reg .u64 t; cvta.to.shared.u64 t, %1; cvt.u32.u64 %0, t; }" : "=r"(a) : "l"(p));
    return a;
}
__device__ __forceinline__ unsigned mapa_smem(unsigned addr, unsigned rank) {
    unsigned r;
    asm("mapa.shared::cluster.u32 %0, %1, %2;" : "=r"(r) : "r"(addr), "r"(rank));
    return r;
}
__device__ __forceinline__ void st_cluster_f32(unsigned addr, float v) {
    asm volatile("st.shared::cluster.f32 [%0], %1;" :: "r"(addr), "f"(v) : "memory");
}
__device__ __forceinline__ void mbar_init(unsigned addr, unsigned cnt) {
    asm volatile("mbarrier.init.shared.b64 [%0], %1;" :: "r"(addr), "r"(cnt) : "memory");
}
__device__ __forceinline__ void mbar_inval(unsigned addr) {
    asm volatile("mbarrier.inval.shared.b64 [%0];" :: "r"(addr) : "memory");
}
__device__ __forceinline__ void mbar_arrive_cluster(unsigned addr) {
    asm volatile("mbarrier.arrive.release.cluster.shared::cluster.b64 _, [%0];"
                 :: "r"(addr) : "memory");
}
__device__ __forceinline__ void mbar_wait_cluster(unsigned mbar, unsigned parity) {
    asm volatile(
        "{\n\t.reg .pred P1;\n\t"
        "WL_%=:\n\t"
        "mbarrier.try_wait.parity.acquire.cluster.shared::cta.b64 P1, [%0], %1, 0x989680;\n\t"
        "@P1 bra.uni WD_%=;\n\t"
        "bra.uni WL_%=;\n\t"
        "WD_%=:\n\t}"
        :: "r"(mbar), "r"(parity) : "memory");
}
#define CLUSTER_SYNC() do { \
    asm volatile("barrier.cluster.arrive.aligned;" ::: "memory"); \
    asm volatile("barrier.cluster.wait.aligned;" ::: "memory"); \
} while (0)

// SMEM layout (bytes from dynamic base)
#define OFF_W32  0          // [128 col][256 k] f32 = 131072
#define OFF_W16  131072     // [128 col][256 k] f16 =  65536
#define OFF_H    196608     // h[2][512] f32          =   4096
#define OFF_Z    200704     // szred[128] f32         =    512
#define OFF_MB   201216     // 2 x u64 mbarrier
#define LSTM_SMEM 201248

// ----------------------------- fast SGEMM: 128x64 tile, 8x4 micro -----------
__global__ void __launch_bounds__(256) sgemm128(
    const float* __restrict__ A, int lda, long sA,
    const float* __restrict__ B, int ldb, long sB,
    float* __restrict__ C, int ldc, long sC,
    int M, int N, int K, const float* __restrict__ bias)
{
    __shared__ float As[16][132];
    __shared__ float Bs[16][64];

    const int tid = threadIdx.x;
    const int tx = tid & 15;
    const int ty = tid >> 4;
    const int m0 = blockIdx.y << 7, n0 = blockIdx.x << 6;
    A += (long)blockIdx.z * sA;
    B += (long)blockIdx.z * sB;
    C += (long)blockIdx.z * sC;

    const int ar = tid >> 2, ac4 = (tid & 3) << 2;
    const int br = tid >> 4, bc4 = (tid & 15) << 2;

    float acc[8][4];
#pragma unroll
    for (int i = 0; i < 8; i++)
#pragma unroll
        for (int j = 0; j < 4; j++) acc[i][j] = 0.f;

    for (int k0 = 0; k0 < K; k0 += 16) {
#pragma unroll
        for (int h = 0; h < 2; h++) {
            int m = ar + (h << 6);
            float4 v = *(const float4*)&A[(long)(m0 + m) * lda + k0 + ac4];
            As[ac4 + 0][m] = v.x;
            As[ac4 + 1][m] = v.y;
            As[ac4 + 2][m] = v.z;
            As[ac4 + 3][m] = v.w;
        }
        float4 bv = make_float4(0.f, 0.f, 0.f, 0.f);
        if (n0 + bc4 + 3 < N) {
            bv = *(const float4*)&B[(long)(k0 + br) * ldb + n0 + bc4];
        } else {
            float* p = (float*)&bv;
#pragma unroll
            for (int c = 0; c < 4; c++)
                if (n0 + bc4 + c < N) p[c] = B[(long)(k0 + br) * ldb + n0 + bc4 + c];
        }
        *(float4*)&Bs[br][bc4] = bv;
        __syncthreads();

#pragma unroll
        for (int k = 0; k < 16; k++) {
            float4 a0 = *(const float4*)&As[k][ty * 8];
            float4 a1 = *(const float4*)&As[k][ty * 8 + 4];
            float4 b4 = *(const float4*)&Bs[k][tx * 4];
            acc[0][0] += a0.x * b4.x; acc[0][1] += a0.x * b4.y; acc[0][2] += a0.x * b4.z; acc[0][3] += a0.x * b4.w;
            acc[1][0] += a0.y * b4.x; acc[1][1] += a0.y * b4.y; acc[1][2] += a0.y * b4.z; acc[1][3] += a0.y * b4.w;
            acc[2][0] += a0.z * b4.x; acc[2][1] += a0.z * b4.y; acc[2][2] += a0.z * b4.z; acc[2][3] += a0.z * b4.w;
            acc[3][0] += a0.w * b4.x; acc[3][1] += a0.w * b4.y; acc[3][2] += a0.w * b4.z; acc[3][3] += a0.w * b4.w;
            acc[4][0] += a1.x * b4.x; acc[4][1] += a1.x * b4.y; acc[4][2] += a1.x * b4.z; acc[4][3] += a1.x * b4.w;
            acc[5][0] += a1.y * b4.x; acc[5][1] += a1.y * b4.y; acc[5][2] += a1.y * b4.z; acc[5][3] += a1.y * b4.w;
            acc[6][0] += a1.z * b4.x; acc[6][1] += a1.z * b4.y; acc[6][2] += a1.z * b4.z; acc[6][3] += a1.z * b4.w;
            acc[7][0] += a1.w * b4.x; acc[7][1] += a1.w * b4.y; acc[7][2] += a1.w * b4.z; acc[7][3] += a1.w * b4.w;
        }
        __syncthreads();
    }

#pragma unroll
    for (int i = 0; i < 8; i++) {
        int m = m0 + ty * 8 + i;
#pragma unroll
        for (int j = 0; j < 4; j++) {
            int n = n0 + tx * 4 + j;
            if (n < N) {
                float v = acc[i][j];
                if (bias) v += bias[n];
                C[(long)m * ldc + n] = v;
            }
        }
    }
}

// ----------------------------- split-K partial reduce ------------------------
__global__ void __launch_bounds__(256) reduce_parts(
    const float* __restrict__ parts, long pstride, int nparts,
    const float* __restrict__ bias, int bmod, float* __restrict__ out, int n)
{
    int i = (blockIdx.x * 256 + threadIdx.x) << 2;
    if (i >= n) return;
    float4 a = *(const float4*)&parts[i];
    for (int p = 1; p < nparts; p++) {
        float4 b = *(const float4*)&parts[(long)p * pstride + i];
        a.x += b.x; a.y += b.y; a.z += b.z; a.w += b.w;
    }
    int bi = i % bmod;
    a.x += bias[bi]; a.y += bias[bi + 1]; a.z += bias[bi + 2]; a.w += bias[bi + 3];
    *(float4*)&out[i] = a;
}

// ----------------------------- persistent LSTM (cluster) --------------------
// 8 clusters x 16 CTAs; cluster = batch. CTA rank owns units [32r, 32r+32)
// = 128 z-cols. W: k<256 fp32 + k>=256 fp16 in SMEM. h exchanged via DSMEM,
// sync via per-CTA mbarrier pairs (release/acquire cluster scope).
__global__ void __launch_bounds__(256) __cluster_dims__(CLSZ, 1, 1)
lstm_cluster_kernel(const float* __restrict__ Wr, float* __restrict__ dout)
{
    extern __shared__ char sm[];
    float* W32 = (float*)(sm + OFF_W32);
    __half* W16 = (__half*)(sm + OFF_W16);
    float* hbuf = (float*)(sm + OFF_H);
    float* szred = (float*)(sm + OFF_Z);
    const unsigned sb = smem_u32(sm);
    const unsigned mb0 = sb + OFF_MB, mb1 = sb + OFF_MB + 8;

    const int tid = threadIdx.x, lane = tid & 31, warp = tid >> 5;
    const int batch = blockIdx.x >> 4;
    const unsigned rank = (unsigned)(blockIdx.x & 15);
    const int u0 = (int)rank << 5;            // first of 32 owned units
    const int c0 = warp << 4;                 // warp's 16 z-cols

    // stage W slice: col = gate*32 + unit_local  <->  Wr col gate*512 + u0 + ul
    for (int idx = tid; idx < 32768; idx += 256) {
        int col = idx >> 8, k = idx & 255;
        int gcol = ((col >> 5) << 9) + u0 + (col & 31);
        W32[col * 256 + k] = Wr[k * 2048 + gcol];
    }
    for (int idx = tid; idx < 32768; idx += 256) {
        int col = idx >> 8, k = idx & 255;
        int gcol = ((col >> 5) << 9) + u0 + (col & 31);
        W16[col * 256 + k] = __float2half(Wr[(k + 256) * 2048 + gcol]);
    }
    for (int i = tid; i < 1024; i += 256) hbuf[i] = 0.f;   // h0 = 0 (both bufs)
    if (tid == 0) { mbar_init(mb0, CLSZ); mbar_init(mb1, CLSZ); }
    __syncthreads();
    CLUSTER_SYNC();   // mbarriers + zeroed h visible cluster-wide

    const float4* w324 = (const float4*)W32;
    const uint4* w16q = (const uint4*)W16;
    float creg = 0.f;

    for (int t = 0; t < TD; t++) {
        // prefetch Xg (overlaps the wait)
        float xg0 = 0.f, xg1 = 0.f, xg2 = 0.f, xg3 = 0.f;
        if (warp == 0) {
            const float* xr = &g_Xg[((batch << 8) + t) * 2048 + u0 + lane];
            xg0 = xr[0]; xg1 = xr[512]; xg2 = xr[1024]; xg3 = xr[1536];
        }
        if (t > 0) {
            unsigned mb = (t & 1) ? mb1 : mb0;
            mbar_wait_cluster(mb, (unsigned)(((t - 1) >> 1) & 1));
        }

        // GEMV: warp computes z[c0..c0+16) over full k=512
        const float4* hb4 = (const float4*)(hbuf + (t & 1) * 512);
        float acc[16];
#pragma unroll
        for (int c = 0; c < 16; c++) acc[c] = 0.f;

#pragma unroll
        for (int j = 0; j < 2; j++) {          // fp32 part: k in [0,256)
            int k4 = (j << 5) + lane;
            float4 h = hb4[k4];
#pragma unroll
            for (int c = 0; c < 16; c++) {
                float4 w = w324[(c0 + c) * 64 + k4];
                acc[c] += h.x * w.x + h.y * w.y + h.z * w.z + h.w * w.w;
            }
        }
        {                                       // fp16 part: k in [256,512)
            float4 ha = hb4[64 + (lane << 1)];
            float4 hc = hb4[64 + (lane << 1) + 1];
#pragma unroll
            for (int c = 0; c < 16; c++) {
                uint4 wq = w16q[(c0 + c) * 32 + lane];
                float2 p0 = __half22float2(*(__half2*)&wq.x);
                float2 p1 = __half22float2(*(__half2*)&wq.y);
                float2 p2 = __half22float2(*(__half2*)&wq.z);
                float2 p3 = __half22float2(*(__half2*)&wq.w);
                acc[c] += p0.x * ha.x + p0.y * ha.y + p1.x * ha.z + p1.y * ha.w
                        + p2.x * hc.x + p2.y * hc.y + p3.x * hc.z + p3.y * hc.w;
            }
        }

        // butterfly over 32 k-lanes
#pragma unroll
        for (int off = 16; off; off >>= 1)
#pragma unroll
            for (int c = 0; c < 16; c++)
                acc[c] += __shfl_xor_sync(0xffffffffu, acc[c], off);
#pragma unroll
        for (int c = 0; c < 16; c++)
            if (lane == c) szred[c0 + c] = acc[c];
        __syncthreads();

        // gates + DSMEM scatter of new h (warp 0; lane = unit_local)
        if (warp == 0) {
            float zi = szred[lane]      + xg0;
            float zf = szred[32 + lane] + xg1;
            float zg = szred[64 + lane] + xg2;
            float zo = szred[96 + lane] + xg3;
            float ig = 1.f / (1.f + __expf(-zi));
            float fg = 1.f / (1.f + __expf(-zf));
            float gg = tanhf(zg);
            float og = 1.f / (1.f + __expf(-zo));
            creg = fg * creg + ig * gg;
            float h = og * tanhf(creg);
            g_XC[((batch << 8) + t) * 1024 + u0 + lane] = h;   // x sequence
            if (t == TD - 1) {
                dout[ROWS * MEL + batch * 512 + u0 + lane] = h;                 // state_h
                dout[ROWS * MEL + BATCH * D + batch * 512 + u0 + lane] = creg;  // state_c
            } else {
                // push h into every peer's buf[(t+1)&1] at my unit offset
                unsigned myoff = sb + OFF_H + (unsigned)((((t + 1) & 1) << 9) + u0 + lane) * 4u;
#pragma unroll
                for (unsigned p = 0; p < CLSZ; p++)
                    st_cluster_f32(mapa_smem(myoff, p), h);
                __syncwarp();
                asm volatile("fence.acq_rel.cluster;" ::: "memory");
                if (lane < CLSZ) {
                    unsigned mymb = ((t + 1) & 1) ? mb1 : mb0;
                    mbar_arrive_cluster(mapa_smem(mymb, (unsigned)lane));
                }
            }
        }
    }

    CLUSTER_SYNC();   // no CTA exits while peers' DSMEM writes may be in flight
    if (tid == 0) { mbar_inval(mb0); mbar_inval(mb1); }
}

// ----------------------------- attention scores -----------------------------
__global__ void __launch_bounds__(256) scores_kernel(const float* __restrict__ W3)
{
    __shared__ float sh1[64 * 65];
    __shared__ float sh2[16 * 64];
    __shared__ float sW3[512];

    const int tid = threadIdx.x;
    const int bz = blockIdx.z, t0 = blockIdx.y << 4, e0 = blockIdx.x << 6;
    const int e = tid & 63, tg = tid >> 6;

    sW3[tid] = W3[tid];
    sW3[tid + 256] = W3[tid + 256];

    float acc[4] = {0.f, 0.f, 0.f, 0.f};

    for (int dc = 0; dc < 512; dc += 64) {
        __syncthreads();
#pragma unroll
        for (int i = 0; i < 4; i++) {
            int q = tid + (i << 8);
            int er = q >> 4, d4 = (q & 15) << 2;
            float4 v = *(const float4*)&g_h1[(long)(bz * 256 + e0 + er) * 512 + dc + d4];
            sh1[(d4 + 0) * 65 + er] = v.x;
            sh1[(d4 + 1) * 65 + er] = v.y;
            sh1[(d4 + 2) * 65 + er] = v.z;
            sh1[(d4 + 3) * 65 + er] = v.w;
        }
        {
            int tt = tid >> 4, d4 = (tid & 15) << 2;
            float4 v = *(const float4*)&g_h2[(long)(bz * 256 + t0 + tt) * 512 + dc + d4];
            *(float4*)&sh2[tt * 64 + d4] = v;
        }
        __syncthreads();

#pragma unroll 8
        for (int d = 0; d < 64; d++) {
            float h1v = sh1[d * 65 + e];
            float w = sW3[dc + d];
#pragma unroll
            for (int i = 0; i < 4; i++) {
                float v = h1v + sh2[(tg * 4 + i) * 64 + d];
                acc[i] += fast_tanh(v) * w;
            }
        }
    }

#pragma unroll
    for (int i = 0; i < 4; i++)
        g_scores[(long)(bz * 256 + t0 + tg * 4 + i) * 256 + e0 + e] = acc[i];
}

// ----------------------------- row softmax (in place) -----------------------
__global__ void __launch_bounds__(256) softmax_kernel()
{
    float* p = g_scores + (long)blockIdx.x * 256;
    const int tid = threadIdx.x;
    const int lane = tid & 31, w = tid >> 5;
    __shared__ float redm[8];
    __shared__ float reds[8];

    float v = p[tid];
    float m = v;
#pragma unroll
    for (int o = 16; o; o >>= 1) m = fmaxf(m, __shfl_xor_sync(0xffffffffu, m, o));
    if (lane == 0) redm[w] = m;
    __syncthreads();
    if (tid < 32) {
        float x = (tid < 8) ? redm[tid] : -1e30f;
#pragma unroll
        for (int o = 4; o; o >>= 1) x = fmaxf(x, __shfl_xor_sync(0xffffffffu, x, o));
        if (tid == 0) redm[0] = x;
    }
    __syncthreads();
    float ev = __expf(v - redm[0]);
    float ssum = ev;
#pragma unroll
    for (int o = 16; o; o >>= 1) ssum += __shfl_xor_sync(0xffffffffu, ssum, o);
    if (lane == 0) reds[w] = ssum;
    __syncthreads();
    if (tid < 32) {
        float x = (tid < 8) ? reds[tid] : 0.f;
#pragma unroll
        for (int o = 4; o; o >>= 1) x += __shfl_xor_sync(0xffffffffu, x, o);
        if (tid == 0) reds[0] = x;
    }
    __syncthreads();
    p[tid] = ev / reds[0];
}

// ----------------------------- launch ---------------------------------------
extern "C" void kernel_launch(void* const* d_in, const int* in_sizes, int n_in,
                              void* d_out, int out_size)
{
    const float* inputs   = (const float*)d_in[0];
    const float* attended = (const float*)d_in[1];
    const float* Wk       = (const float*)d_in[2];
    const float* Wr       = (const float*)d_in[3];
    const float* lstm_b   = (const float*)d_in[4];
    const float* W1       = (const float*)d_in[5];
    const float* b1       = (const float*)d_in[6];
    const float* W3       = (const float*)d_in[7];
    /* b3 (d_in[8]) cancels in softmax */
    const float* Wout     = (const float*)d_in[9];
    const float* bout     = (const float*)d_in[10];
    float* dout = (float*)d_out;

    static float* pXg = nullptr;
    static float* pH1 = nullptr;
    static float* pH2 = nullptr;
    static float* pXC = nullptr;
    static float* pSc = nullptr;
    static float* pPt = nullptr;
    static bool attr_done = false;
    if (!pXg) {
        cudaGetSymbolAddress((void**)&pXg, g_Xg);
        cudaGetSymbolAddress((void**)&pH1, g_h1);
        cudaGetSymbolAddress((void**)&pH2, g_h2);
        cudaGetSymbolAddress((void**)&pXC, g_XC);
        cudaGetSymbolAddress((void**)&pSc, g_scores);
        cudaGetSymbolAddress((void**)&pPt, g_part);
    }
    if (!attr_done) {
        cudaFuncSetAttribute(lstm_cluster_kernel,
                             cudaFuncAttributeNonPortableClusterSizeAllowed, 1);
        cudaFuncSetAttribute(lstm_cluster_kernel,
                             cudaFuncAttributeMaxDynamicSharedMemorySize, LSTM_SMEM);
        attr_done = true;
    }
    const long PS = (long)ROWS * D;

    // 1. Xg = inputs @ Wk + lstm_b              [2048,2048] K=80
    sgemm128<<<dim3(32, 16, 1), 256>>>(inputs, DIN, 0, Wk, 4 * D, 0,
                                       pXg, 4 * D, 0, ROWS, 4 * D, DIN, lstm_b);
    // 2. h1 = attended @ W1 + b1  (split-K 2)
    sgemm128<<<dim3(8, 16, 2), 256>>>(attended, D, 256, W1, D, 256L * D,
                                      pPt, D, PS, ROWS, D, 256, nullptr);
    reduce_parts<<<PS / 1024, 256>>>(pPt, PS, 2, b1, D, pH1, (int)PS);
    // 3. LSTM: 8 clusters x 16 CTAs, DSMEM h exchange + mbarrier sync
    lstm_cluster_kernel<<<128, 256, LSTM_SMEM>>>(Wr, dout);
    // 4. h2 = x @ W1 + b1  (split-K 2)
    sgemm128<<<dim3(8, 16, 2), 256>>>(pXC, 2 * D, 256, W1, D, 256L * D,
                                      pPt, D, PS, ROWS, D, 256, nullptr);
    reduce_parts<<<PS / 1024, 256>>>(pPt, PS, 2, b1, D, pH2, (int)PS);
    // 5. scores
    scores_kernel<<<dim3(4, 16, 8), 256>>>(W3);
    // 6. softmax (in place -> attn)
    softmax_kernel<<<ROWS, 256>>>();
    // 7. weighted = attn @ attended  (batched over z) -> g_XC[:, 512:]
    sgemm128<<<dim3(8, 2, 8), 256>>>(pSc, TE, (long)TD * TE,
                                     attended, D, (long)TE * D,
                                     pXC + D, 2 * D, (long)TD * 2 * D,
                                     TD, D, TE, nullptr);
    // 8. out = [x | weighted] @ Wout + bout  (split-K 4)
    {
        const long OS = (long)ROWS * MEL;
        sgemm128<<<dim3(2, 16, 4), 256>>>(pXC, 2 * D, 256, Wout, MEL, 256L * MEL,
                                          pPt, MEL, OS, ROWS, MEL, 256, nullptr);
        reduce_parts<<<(unsigned)(OS / 1024), 256>>>(pPt, OS, 4, bout, MEL, dout, (int)OS);
    }
}

// round 9
// speedup vs baseline: 1.6307x; 1.6307x over previous
#include <cuda_runtime.h>
#include <math.h>

#define BATCH 8
#define TD 256
#define TE 256
#define DIN 80
#define D 512
#define MEL 80
#define ROWS (BATCH*TD)          // 2048
#define NBLK_LSTM 128
#define POISON 0x7FC0DEADu      // NaN payload; never produced by finite math

// ----------------------------- scratch (device globals) ---------------------
__device__ __align__(16) float g_Xg[ROWS * 4 * D];        // inputs@Wk + b : [2048][2048]
__device__ __align__(16) float g_h1[ROWS * D];            // attended@W1+b1: [2048][512]
__device__ __align__(16) float g_h2[ROWS * D];            // x@W1+b1      : [2048][512]
__device__ __align__(16) float g_XC[ROWS * 2 * D];        // [x | weighted]: [2048][1024]
__device__ __align__(16) float g_scores[BATCH * TD * TE]; // scores/attn   : [2048][256]
__device__ __align__(16) float g_part[4 * ROWS * D];      // split-K partials
__device__ __align__(16) float g_hstep[257 * BATCH * D];  // step-indexed h: [257][8][512]
__device__ unsigned g_flags[NBLK_LSTM * 8];               // prologue barrier flags

// ----------------------------- helpers --------------------------------------
__device__ __forceinline__ float fast_tanh(float x) {
    float y;
    asm("tanh.approx.f32 %0, %1;" : "=f"(y) : "f"(x));
    return y;
}
__device__ __forceinline__ unsigned ldg_relaxed_u32(const unsigned* p) {
    unsigned v;
    asm volatile("ld.relaxed.gpu.global.u32 %0, [%1];" : "=r"(v) : "l"(p) : "memory");
    return v;
}
__device__ __forceinline__ void stg_relaxed_u32(unsigned* p, unsigned v) {
    asm volatile("st.relaxed.gpu.global.u32 [%0], %1;" :: "l"(p), "r"(v) : "memory");
}
__device__ __forceinline__ float4 ldg_relaxed_f4(const float4* p) {
    float4 v;
    asm volatile("ld.relaxed.gpu.global.v4.f32 {%0,%1,%2,%3}, [%4];"
                 : "=f"(v.x), "=f"(v.y), "=f"(v.z), "=f"(v.w) : "l"(p) : "memory");
    return v;
}
__device__ __forceinline__ void stg_relaxed_f4(float4* p, float4 v) {
    asm volatile("st.relaxed.gpu.global.v4.f32 [%0], {%1,%2,%3,%4};"
                 :: "l"(p), "f"(v.x), "f"(v.y), "f"(v.z), "f"(v.w) : "memory");
}
__device__ __forceinline__ void fence_gpu() {
    asm volatile("fence.acq_rel.gpu;" ::: "memory");
}
__device__ __forceinline__ bool not_poison(float4 v) {
    return (__float_as_uint(v.x) != POISON) & (__float_as_uint(v.y) != POISON) &
           (__float_as_uint(v.z) != POISON) & (__float_as_uint(v.w) != POISON);
}
__device__ __forceinline__ float sigm_e(float x) { return 1.f / (1.f + __expf(-x)); }
__device__ __forceinline__ float tanh_e(float x) { return 1.f - 2.f / (1.f + __expf(2.f * x)); }

// ----------------------------- fast SGEMM: 128x64 tile, 8x4 micro -----------
__global__ void __launch_bounds__(256) sgemm128(
    const float* __restrict__ A, int lda, long sA,
    const float* __restrict__ B, int ldb, long sB,
    float* __restrict__ C, int ldc, long sC,
    int M, int N, int K, const float* __restrict__ bias)
{
    __shared__ float As[16][132];
    __shared__ float Bs[16][64];

    const int tid = threadIdx.x;
    const int tx = tid & 15;
    const int ty = tid >> 4;
    const int m0 = blockIdx.y << 7, n0 = blockIdx.x << 6;
    A += (long)blockIdx.z * sA;
    B += (long)blockIdx.z * sB;
    C += (long)blockIdx.z * sC;

    const int ar = tid >> 2, ac4 = (tid & 3) << 2;
    const int br = tid >> 4, bc4 = (tid & 15) << 2;

    float acc[8][4];
#pragma unroll
    for (int i = 0; i < 8; i++)
#pragma unroll
        for (int j = 0; j < 4; j++) acc[i][j] = 0.f;

    for (int k0 = 0; k0 < K; k0 += 16) {
#pragma unroll
        for (int h = 0; h < 2; h++) {
            int m = ar + (h << 6);
            float4 v = *(const float4*)&A[(long)(m0 + m) * lda + k0 + ac4];
            As[ac4 + 0][m] = v.x;
            As[ac4 + 1][m] = v.y;
            As[ac4 + 2][m] = v.z;
            As[ac4 + 3][m] = v.w;
        }
        float4 bv = make_float4(0.f, 0.f, 0.f, 0.f);
        if (n0 + bc4 + 3 < N) {
            bv = *(const float4*)&B[(long)(k0 + br) * ldb + n0 + bc4];
        } else {
            float* p = (float*)&bv;
#pragma unroll
            for (int c = 0; c < 4; c++)
                if (n0 + bc4 + c < N) p[c] = B[(long)(k0 + br) * ldb + n0 + bc4 + c];
        }
        *(float4*)&Bs[br][bc4] = bv;
        __syncthreads();

#pragma unroll
        for (int k = 0; k < 16; k++) {
            float4 a0 = *(const float4*)&As[k][ty * 8];
            float4 a1 = *(const float4*)&As[k][ty * 8 + 4];
            float4 b4 = *(const float4*)&Bs[k][tx * 4];
            acc[0][0] += a0.x * b4.x; acc[0][1] += a0.x * b4.y; acc[0][2] += a0.x * b4.z; acc[0][3] += a0.x * b4.w;
            acc[1][0] += a0.y * b4.x; acc[1][1] += a0.y * b4.y; acc[1][2] += a0.y * b4.z; acc[1][3] += a0.y * b4.w;
            acc[2][0] += a0.z * b4.x; acc[2][1] += a0.z * b4.y; acc[2][2] += a0.z * b4.z; acc[2][3] += a0.z * b4.w;
            acc[3][0] += a0.w * b4.x; acc[3][1] += a0.w * b4.y; acc[3][2] += a0.w * b4.z; acc[3][3] += a0.w * b4.w;
            acc[4][0] += a1.x * b4.x; acc[4][1] += a1.x * b4.y; acc[4][2] += a1.x * b4.z; acc[4][3] += a1.x * b4.w;
            acc[5][0] += a1.y * b4.x; acc[5][1] += a1.y * b4.y; acc[5][2] += a1.y * b4.z; acc[5][3] += a1.y * b4.w;
            acc[6][0] += a1.z * b4.x; acc[6][1] += a1.z * b4.y; acc[6][2] += a1.z * b4.z; acc[6][3] += a1.z * b4.w;
            acc[7][0] += a1.w * b4.x; acc[7][1] += a1.w * b4.y; acc[7][2] += a1.w * b4.z; acc[7][3] += a1.w * b4.w;
        }
        __syncthreads();
    }

#pragma unroll
    for (int i = 0; i < 8; i++) {
        int m = m0 + ty * 8 + i;
#pragma unroll
        for (int j = 0; j < 4; j++) {
            int n = n0 + tx * 4 + j;
            if (n < N) {
                float v = acc[i][j];
                if (bias) v += bias[n];
                C[(long)m * ldc + n] = v;
            }
        }
    }
}

// ----------------------------- split-K partial reduce ------------------------
__global__ void __launch_bounds__(256) reduce_parts(
    const float* __restrict__ parts, long pstride, int nparts,
    const float* __restrict__ bias, int bmod, float* __restrict__ out, int n)
{
    int i = (blockIdx.x * 256 + threadIdx.x) << 2;
    if (i >= n) return;
    float4 a = *(const float4*)&parts[i];
    for (int p = 1; p < nparts; p++) {
        float4 b = *(const float4*)&parts[(long)p * pstride + i];
        a.x += b.x; a.y += b.y; a.z += b.z; a.w += b.w;
    }
    int bi = i % bmod;
    a.x += bias[bi]; a.y += bias[bi + 1]; a.z += bias[bi + 2]; a.w += bias[bi + 3];
    *(float4*)&out[i] = a;
}

// ----------------------------- persistent LSTM (poison-poll) ----------------
// 128 CTAs x 256 threads. CTA owns units [4c, 4c+4). Per step, producers write
// their h line per batch; consumers poll the float4s directly (data = flag).
// One flag barrier at prologue only.
__global__ void __launch_bounds__(256) lstm_kernel(
    const float* __restrict__ Wr, float* __restrict__ dout)
{
    extern __shared__ float s[];
    float* sWr = s;                         // [16 cols][512 k]
    float* sh = s + 8192;                   // [8 b][512 k]
    float* szred = s + 8192 + 4096;         // [8 b][16 c] (also reused for h-gather)
    const float4* sWrv = (const float4*)sWr;
    float4* shv = (float4*)sh;
    __shared__ unsigned s_base;

    const int tid = threadIdx.x;
    const int hu0 = blockIdx.x << 2;
    const int lane = tid & 31, warp = tid >> 5;
    const int cb = warp & 3, bb = warp >> 2;  // col-block (=gate), batch-block
    const int gb = tid >> 2, gu = tid & 3;    // gate-thread mapping (tid<32)

    // load Wr slice once: sWr[c*512+k] = Wr[k][512*gate + hu0 + u]
    for (int idx = tid; idx < 8192; idx += 256) {
        int c = idx >> 9, k = idx & 511;
        int col = ((c >> 2) << 9) + hu0 + (c & 3);
        sWr[idx] = Wr[k * 2048 + col];
    }

    // prologue: poison own lines of buf[1..256]; zeros into buf[0]
    {
        uint4 pz = make_uint4(POISON, POISON, POISON, POISON);
        for (int i = tid; i < 256 * 8; i += 256) {
            int t1 = (i >> 3) + 1, b = i & 7;
            *(uint4*)&g_hstep[((t1 * 8 + b) * 512) + hu0] = pz;
        }
        if (tid < 8) *(float4*)&g_hstep[(tid * 512) + hu0] = make_float4(0.f, 0.f, 0.f, 0.f);
    }
    if (tid == 0) s_base = ldg_relaxed_u32(&g_flags[blockIdx.x * 8]);
    __syncthreads();
    const unsigned base = s_base;
    if (tid == 0) { fence_gpu(); stg_relaxed_u32(&g_flags[blockIdx.x * 8], base + 1u); }
    if (warp == 0) {                         // one-shot grid barrier
        const unsigned tgt = base + 1u;
        bool ok;
        do {
            unsigned f0 = ldg_relaxed_u32(&g_flags[(lane) * 8]);
            unsigned f1 = ldg_relaxed_u32(&g_flags[(lane + 32) * 8]);
            unsigned f2 = ldg_relaxed_u32(&g_flags[(lane + 64) * 8]);
            unsigned f3 = ldg_relaxed_u32(&g_flags[(lane + 96) * 8]);
            ok = ((int)(f0 - tgt) >= 0) & ((int)(f1 - tgt) >= 0) &
                 ((int)(f2 - tgt) >= 0) & ((int)(f3 - tgt) >= 0);
        } while (!__all_sync(0xffffffffu, ok));
        fence_gpu();
    }
    __syncthreads();

    float creg = 0.f;

    for (int t = 0; t < TD; t++) {
        // prefetch Xg for this step (overlaps the poll)
        float xg0 = 0.f, xg1 = 0.f, xg2 = 0.f, xg3 = 0.f;
        if (tid < 32) {
            const float* xr = &g_Xg[((gb << 8) + t) * 2048 + hu0 + gu];
            xg0 = xr[0]; xg1 = xr[512]; xg2 = xr[1024]; xg3 = xr[1536];
        }

        // stage h(t): poll 4 float4 lines per thread until non-poison
        {
            const float4* src = (const float4*)&g_hstep[t * (BATCH * D)];
            float4 v0, v1, v2, v3;
            unsigned done = 0;
            do {
                if (!(done & 1u)) { float4 x = ldg_relaxed_f4(src + tid);        if (not_poison(x)) { v0 = x; done |= 1u; } }
                if (!(done & 2u)) { float4 x = ldg_relaxed_f4(src + tid + 256);  if (not_poison(x)) { v1 = x; done |= 2u; } }
                if (!(done & 4u)) { float4 x = ldg_relaxed_f4(src + tid + 512);  if (not_poison(x)) { v2 = x; done |= 4u; } }
                if (!(done & 8u)) { float4 x = ldg_relaxed_f4(src + tid + 768);  if (not_poison(x)) { v3 = x; done |= 8u; } }
            } while (done != 0xFu);
            shv[tid] = v0; shv[tid + 256] = v1; shv[tid + 512] = v2; shv[tid + 768] = v3;
        }
        __syncthreads();

        // GEMV: warp (cb,bb) computes z[bb*4..+3][cb*4..+3], k lane-vectorized
        float acc[4][4];
#pragma unroll
        for (int i = 0; i < 4; i++)
#pragma unroll
            for (int j = 0; j < 4; j++) acc[i][j] = 0.f;

#pragma unroll
        for (int kk = 0; kk < 4; kk++) {
            const int kv = (kk << 5) + lane;
            float4 h0 = shv[((bb << 2) + 0) * 128 + kv];
            float4 h1 = shv[((bb << 2) + 1) * 128 + kv];
            float4 h2 = shv[((bb << 2) + 2) * 128 + kv];
            float4 h3 = shv[((bb << 2) + 3) * 128 + kv];
            float4 w0 = sWrv[((cb << 2) + 0) * 128 + kv];
            float4 w1 = sWrv[((cb << 2) + 1) * 128 + kv];
            float4 w2 = sWrv[((cb << 2) + 2) * 128 + kv];
            float4 w3 = sWrv[((cb << 2) + 3) * 128 + kv];
#define DOT4(a,b) ((a).x*(b).x + (a).y*(b).y + (a).z*(b).z + (a).w*(b).w)
            acc[0][0] += DOT4(h0, w0); acc[0][1] += DOT4(h0, w1); acc[0][2] += DOT4(h0, w2); acc[0][3] += DOT4(h0, w3);
            acc[1][0] += DOT4(h1, w0); acc[1][1] += DOT4(h1, w1); acc[1][2] += DOT4(h1, w2); acc[1][3] += DOT4(h1, w3);
            acc[2][0] += DOT4(h2, w0); acc[2][1] += DOT4(h2, w1); acc[2][2] += DOT4(h2, w2); acc[2][3] += DOT4(h2, w3);
            acc[3][0] += DOT4(h3, w0); acc[3][1] += DOT4(h3, w1); acc[3][2] += DOT4(h3, w2); acc[3][3] += DOT4(h3, w3);
#undef DOT4
        }

        // butterfly reduce over 32 k-lanes
#pragma unroll
        for (int off = 16; off; off >>= 1)
#pragma unroll
            for (int i = 0; i < 4; i++)
#pragma unroll
                for (int j = 0; j < 4; j++)
                    acc[i][j] += __shfl_xor_sync(0xffffffffu, acc[i][j], off);

        if (lane < 16) {
            int i = lane >> 2, j = lane & 3;
            szred[((bb << 2) + i) * 16 + ((cb << 2) + j)] = acc[i][j];
        }
        __syncthreads();

        // gates on warp 0; other warps fall through to next step's polling.
        if (tid < 32) {
            float zi = szred[gb * 16 + 0 + gu] + xg0;
            float zf = szred[gb * 16 + 4 + gu] + xg1;
            float zg = szred[gb * 16 + 8 + gu] + xg2;
            float zo = szred[gb * 16 + 12 + gu] + xg3;
            float ig = sigm_e(zi);
            float fg = sigm_e(zf);
            float gg = tanh_e(zg);
            float og = sigm_e(zo);
            creg = fg * creg + ig * gg;
            float h = og * tanh_e(creg);
            g_XC[((gb << 8) + t) * 1024 + hu0 + gu] = h;   // x sequence
            if (t == TD - 1) {
                dout[ROWS * MEL + gb * 512 + hu0 + gu] = h;                 // state_h
                dout[ROWS * MEL + BATCH * D + gb * 512 + hu0 + gu] = creg;  // state_c
            }
            // gather 4 unit-values per batch into one line, publish via one st.v4
            szred[tid] = h;                    // szred[gb*4+gu]; safe (see sync layout)
            __syncwarp();
            if (lane < 8) {
                float4 hl = *(const float4*)&szred[lane << 2];
                stg_relaxed_f4((float4*)&g_hstep[(((t + 1) * 8 + lane) * 512) + hu0], hl);
            }
        }
        // no grid sync: buf[t+1] data itself is the flag
    }
}

// ----------------------------- attention scores -----------------------------
__global__ void __launch_bounds__(256) scores_kernel(const float* __restrict__ W3)
{
    __shared__ float sh1[64 * 65];
    __shared__ float sh2[16 * 64];
    __shared__ float sW3[512];

    const int tid = threadIdx.x;
    const int bz = blockIdx.z, t0 = blockIdx.y << 4, e0 = blockIdx.x << 6;
    const int e = tid & 63, tg = tid >> 6;

    sW3[tid] = W3[tid];
    sW3[tid + 256] = W3[tid + 256];

    float acc[4] = {0.f, 0.f, 0.f, 0.f};

    for (int dc = 0; dc < 512; dc += 64) {
        __syncthreads();
#pragma unroll
        for (int i = 0; i < 4; i++) {
            int q = tid + (i << 8);
            int er = q >> 4, d4 = (q & 15) << 2;
            float4 v = *(const float4*)&g_h1[(long)(bz * 256 + e0 + er) * 512 + dc + d4];
            sh1[(d4 + 0) * 65 + er] = v.x;
            sh1[(d4 + 1) * 65 + er] = v.y;
            sh1[(d4 + 2) * 65 + er] = v.z;
            sh1[(d4 + 3) * 65 + er] = v.w;
        }
        {
            int tt = tid >> 4, d4 = (tid & 15) << 2;
            float4 v = *(const float4*)&g_h2[(long)(bz * 256 + t0 + tt) * 512 + dc + d4];
            *(float4*)&sh2[tt * 64 + d4] = v;
        }
        __syncthreads();

#pragma unroll 8
        for (int d = 0; d < 64; d++) {
            float h1v = sh1[d * 65 + e];
            float w = sW3[dc + d];
#pragma unroll
            for (int i = 0; i < 4; i++) {
                float v = h1v + sh2[(tg * 4 + i) * 64 + d];
                acc[i] += fast_tanh(v) * w;
            }
        }
    }

#pragma unroll
    for (int i = 0; i < 4; i++)
        g_scores[(long)(bz * 256 + t0 + tg * 4 + i) * 256 + e0 + e] = acc[i];
}

// ----------------------------- row softmax (in place) -----------------------
__global__ void __launch_bounds__(256) softmax_kernel()
{
    float* p = g_scores + (long)blockIdx.x * 256;
    const int tid = threadIdx.x;
    const int lane = tid & 31, w = tid >> 5;
    __shared__ float redm[8];
    __shared__ float reds[8];

    float v = p[tid];
    float m = v;
#pragma unroll
    for (int o = 16; o; o >>= 1) m = fmaxf(m, __shfl_xor_sync(0xffffffffu, m, o));
    if (lane == 0) redm[w] = m;
    __syncthreads();
    if (tid < 32) {
        float x = (tid < 8) ? redm[tid] : -1e30f;
#pragma unroll
        for (int o = 4; o; o >>= 1) x = fmaxf(x, __shfl_xor_sync(0xffffffffu, x, o));
        if (tid == 0) redm[0] = x;
    }
    __syncthreads();
    float ev = __expf(v - redm[0]);
    float ssum = ev;
#pragma unroll
    for (int o = 16; o; o >>= 1) ssum += __shfl_xor_sync(0xffffffffu, ssum, o);
    if (lane == 0) reds[w] = ssum;
    __syncthreads();
    if (tid < 32) {
        float x = (tid < 8) ? reds[tid] : 0.f;
#pragma unroll
        for (int o = 4; o; o >>= 1) x += __shfl_xor_sync(0xffffffffu, x, o);
        if (tid == 0) reds[0] = x;
    }
    __syncthreads();
    p[tid] = ev / reds[0];
}

// ----------------------------- launch ---------------------------------------
extern "C" void kernel_launch(void* const* d_in, const int* in_sizes, int n_in,
                              void* d_out, int out_size)
{
    const float* inputs   = (const float*)d_in[0];
    const float* attended = (const float*)d_in[1];
    const float* Wk       = (const float*)d_in[2];
    const float* Wr       = (const float*)d_in[3];
    const float* lstm_b   = (const float*)d_in[4];
    const float* W1       = (const float*)d_in[5];
    const float* b1       = (const float*)d_in[6];
    const float* W3       = (const float*)d_in[7];
    /* b3 (d_in[8]) cancels in softmax */
    const float* Wout     = (const float*)d_in[9];
    const float* bout     = (const float*)d_in[10];
    float* dout = (float*)d_out;

    static float* pXg = nullptr;
    static float* pH1 = nullptr;
    static float* pH2 = nullptr;
    static float* pXC = nullptr;
    static float* pSc = nullptr;
    static float* pPt = nullptr;
    static bool attr_done = false;
    if (!pXg) {
        cudaGetSymbolAddress((void**)&pXg, g_Xg);
        cudaGetSymbolAddress((void**)&pH1, g_h1);
        cudaGetSymbolAddress((void**)&pH2, g_h2);
        cudaGetSymbolAddress((void**)&pXC, g_XC);
        cudaGetSymbolAddress((void**)&pSc, g_scores);
        cudaGetSymbolAddress((void**)&pPt, g_part);
    }
    if (!attr_done) {
        cudaFuncSetAttribute(lstm_kernel, cudaFuncAttributeMaxDynamicSharedMemorySize, 50176);
        attr_done = true;
    }
    const long PS = (long)ROWS * D;

    // 1. Xg = inputs @ Wk + lstm_b              [2048,2048] K=80
    sgemm128<<<dim3(32, 16, 1), 256>>>(inputs, DIN, 0, Wk, 4 * D, 0,
                                       pXg, 4 * D, 0, ROWS, 4 * D, DIN, lstm_b);
    // 2. h1 = attended @ W1 + b1  (split-K 2)
    sgemm128<<<dim3(8, 16, 2), 256>>>(attended, D, 256, W1, D, 256L * D,
                                      pPt, D, PS, ROWS, D, 256, nullptr);
    reduce_parts<<<PS / 1024, 256>>>(pPt, PS, 2, b1, D, pH1, (int)PS);
    // 3. LSTM (persistent, poison-poll handshake)
    lstm_kernel<<<NBLK_LSTM, 256, 50176>>>(Wr, dout);
    // 4. h2 = x @ W1 + b1  (split-K 2)
    sgemm128<<<dim3(8, 16, 2), 256>>>(pXC, 2 * D, 256, W1, D, 256L * D,
                                      pPt, D, PS, ROWS, D, 256, nullptr);
    reduce_parts<<<PS / 1024, 256>>>(pPt, PS, 2, b1, D, pH2, (int)PS);
    // 5. scores
    scores_kernel<<<dim3(4, 16, 8), 256>>>(W3);
    // 6. softmax (in place -> attn)
    softmax_kernel<<<ROWS, 256>>>();
    // 7. weighted = attn @ attended  (batched over z) -> g_XC[:, 512:]
    sgemm128<<<dim3(8, 2, 8), 256>>>(pSc, TE, (long)TD * TE,
                                     attended, D, (long)TE * D,
                                     pXC + D, 2 * D, (long)TD * 2 * D,
                                     TD, D, TE, nullptr);
    // 8. out = [x | weighted] @ Wout + bout  (split-K 4)
    {
        const long OS = (long)ROWS * MEL;
        sgemm128<<<dim3(2, 16, 4), 256>>>(pXC, 2 * D, 256, Wout, MEL, 256L * MEL,
                                          pPt, MEL, OS, ROWS, MEL, 256, nullptr);
        reduce_parts<<<(unsigned)(OS / 1024), 256>>>(pPt, OS, 4, bout, MEL, dout, (int)OS);
    }
}